// round 13
// baseline (speedup 1.0000x reference)
#include <cuda_runtime.h>
#include <cuda_fp16.h>
#include <math.h>
#include <stdint.h>

#define BB 4
#define TT 1024
#define CC 2048
#define HH 32
#define NNd 64
#define KVD 512
#define MM (BB*TT)      // 4096 tokens
#define N1 3328         // combined GEMM1 N: 2048(R)+512(K)+512(V)+160(lora)+96 pad
#define HIDP 192        // hidden padded cols

// ---------------- scratch (static device arrays; no allocation) ----------------
__device__ __align__(128) __half g_xh[(size_t)MM*CC];
__device__ __align__(128) __half g_b1hi[(size_t)N1*CC];
__device__ __align__(128) __half g_b1lo[(size_t)N1*CC];
__device__ __align__(128) float g_bias1[N1];
__device__ __align__(128) float g_proj[(size_t)MM*N1];
__device__ __align__(128) __half g_hidh[(size_t)MM*HIDP];
__device__ __align__(128) __half g_w2hi[CC*64];
__device__ __align__(128) __half g_w2lo[CC*64];
__device__ __align__(128) __half g_a2hi[CC*64];
__device__ __align__(128) __half g_a2lo[CC*64];
__device__ __align__(128) __half g_v2hi[CC*64];
__device__ __align__(128) __half g_v2lo[CC*64];
__device__ __align__(128) float g_wterm[(size_t)MM*CC];
__device__ __align__(128) float g_aterm[(size_t)MM*CC];
__device__ __align__(128) float g_vterm[(size_t)MM*CC];
__device__ __align__(128) float g_packed[(size_t)BB*HH*TT*384];
__device__ __align__(128) float g_y[(size_t)MM*CC];      // layout (b,h,t,i)
__device__ __align__(128) __half g_xxh[(size_t)MM*CC];
__device__ __align__(128) __half g_ohi[(size_t)CC*CC];
__device__ __align__(128) __half g_olo[(size_t)CC*CC];
__device__ __align__(128) float g_bcoef[(size_t)MM*HH];
__device__ __align__(128) float g_gn[BB*HH*2];

// ---------------- helpers ----------------
__device__ __forceinline__ float sigmoidf_(float x){ return 1.0f/(1.0f + expf(-x)); }

__device__ __forceinline__ void cp_async16(void* smem, const void* gmem){
    unsigned s = (unsigned)__cvta_generic_to_shared(smem);
    asm volatile("cp.async.cg.shared.global [%0], [%1], 16;\n" :: "r"(s), "l"(gmem));
}

__device__ __forceinline__ void split2h(float v, __half* hi, __half* lo){
    __half h = __float2half_rn(v);
    *hi = h;
    *lo = __float2half_rn(v - __half2float(h));
}

// ---------------- mma.sync helpers (legacy tensor path; plain sm_103 target) ----
__device__ __forceinline__ void ldsm4(uint32_t* r, uint32_t addr){
    asm volatile("ldmatrix.sync.aligned.m8n8.x4.shared.b16 {%0,%1,%2,%3}, [%4];"
                 : "=r"(r[0]), "=r"(r[1]), "=r"(r[2]), "=r"(r[3]) : "r"(addr));
}

__device__ __forceinline__ void mma16816(float* c, const uint32_t* a, const uint32_t* b){
    asm volatile(
        "mma.sync.aligned.m16n8k16.row.col.f32.f16.f16.f32 "
        "{%0,%1,%2,%3}, {%4,%5,%6,%7}, {%8,%9}, {%0,%1,%2,%3};"
        : "+f"(c[0]), "+f"(c[1]), "+f"(c[2]), "+f"(c[3])
        : "r"(a[0]), "r"(a[1]), "r"(a[2]), "r"(a[3]), "r"(b[0]), "r"(b[1]));
}

// ---------------- packing / convert kernels ----------------
__global__ void pack_b1(const float* __restrict__ R,  const float* __restrict__ Rb,
                        const float* __restrict__ Kw, const float* __restrict__ Kb,
                        const float* __restrict__ Vw, const float* __restrict__ Vb,
                        const float* __restrict__ w1, const float* __restrict__ a1,
                        const float* __restrict__ v1)
{
    size_t idx = (size_t)blockIdx.x*blockDim.x + threadIdx.x;
    if (idx < N1) {
        float bv = 0.f;
        if (idx < 2048) bv = Rb[idx];
        else if (idx < 2560) bv = Kb[idx-2048];
        else if (idx < 3072) bv = Vb[idx-2560];
        g_bias1[idx] = bv;
    }
    if (idx >= (size_t)N1*CC) return;
    int n = (int)(idx / CC), k = (int)(idx % CC);
    float v = 0.f;
    if      (n < 2048) v = R [(size_t)n*CC + k];
    else if (n < 2560) v = Kw[(size_t)(n-2048)*CC + k];
    else if (n < 3072) v = Vw[(size_t)(n-2560)*CC + k];
    else if (n < 3136) v = w1[(size_t)k*64 + (n-3072)];
    else if (n < 3200) v = a1[(size_t)k*64 + (n-3136)];
    else if (n < 3232) v = v1[(size_t)k*32 + (n-3200)];
    split2h(v, &g_b1hi[idx], &g_b1lo[idx]);
}

__global__ void pack_b2(const float* __restrict__ w2, const float* __restrict__ a2,
                        const float* __restrict__ v2)
{
    int idx = blockIdx.x*blockDim.x + threadIdx.x;
    if (idx >= CC*64) return;
    int n = idx / 64, k = idx % 64;
    split2h(w2[(size_t)k*CC + n], &g_w2hi[idx], &g_w2lo[idx]);
    split2h(a2[(size_t)k*CC + n], &g_a2hi[idx], &g_a2lo[idx]);
    float vv = (k < 32) ? v2[(size_t)k*CC + n] : 0.f;
    split2h(vv, &g_v2hi[idx], &g_v2lo[idx]);
}

// merged: split Ow into hi/lo AND convert x to fp16
__global__ void split_ox(const float* __restrict__ Ow, const float* __restrict__ x)
{
    size_t stride = (size_t)gridDim.x * blockDim.x;
    size_t i0 = (size_t)blockIdx.x*blockDim.x + threadIdx.x;
    for (size_t i = i0; i < (size_t)CC*CC; i += stride)
        split2h(Ow[i], &g_ohi[i], &g_olo[i]);
    for (size_t i = i0; i < (size_t)MM*CC/4; i += stride){
        float4 v = *(const float4*)(x + i*4);
        __half h[4] = {__float2half_rn(v.x), __float2half_rn(v.y),
                       __float2half_rn(v.z), __float2half_rn(v.w)};
        *(uint2*)(g_xh + i*4) = *(uint2*)h;
    }
}

__global__ void hid_cvt()
{
    size_t idx = (size_t)blockIdx.x*blockDim.x + threadIdx.x;
    if (idx >= (size_t)MM*HIDP) return;
    int m = (int)(idx / HIDP), j = (int)(idx % HIDP);
    const float* row = g_proj + (size_t)m*N1 + 3072;
    float v = 0.f;
    if (j < 64)       v = tanhf(row[j]);
    else if (j < 160) v = row[j];
    g_hidh[idx] = __float2half_rn(v);
}

// ---------------- fp16 2-product HMMA NT GEMM: C = Ah*(Bhi+Blo)^T + bias --------
// BM=BN=128, BK=32, 256 threads (8 warps, warp tile 64x32).
// 3-stage cp.async ring, ONE __syncthreads per K-tile.
#define SPAD 40                     // smem row stride in fp16 elems (32 + 8 pad)
#define TILEB (128*SPAD*2)          // 10240 B per operand tile
#define STAGEB (3*TILEB)            // 30720 B per stage (A, Bhi, Blo)
#define NSTAGE 3

__global__ void __launch_bounds__(256,2) hmma_nt(
    const __half* __restrict__ Ah, int lda,
    const __half* __restrict__ Bhi, const __half* __restrict__ Blo, int ldb,
    const float* __restrict__ bias, float* __restrict__ Cc, int ldc, int KT)
{
    extern __shared__ __align__(128) char smem[];
    const int tid  = threadIdx.x;
    const int warp = tid >> 5;
    const int lane = tid & 31;
    const int bm   = blockIdx.y * 128;
    const int bn   = blockIdx.x * 128;
    const int wm   = (warp & 1) * 64;
    const int wn   = (warp >> 1) * 32;

    float acc[4][4][4];
    #pragma unroll
    for (int a=0;a<4;a++)
        #pragma unroll
        for (int b=0;b<4;b++)
            #pragma unroll
            for (int c=0;c<4;c++) acc[a][b][c]=0.f;

    auto load_stage = [&](int stage, int kt){
        const int k0 = kt * 32;
        char* sb = smem + stage * STAGEB;
        const __half* bases[3];
        int lds[3];
        bases[0] = Ah  + (size_t)bm*lda + k0; lds[0] = lda;
        bases[1] = Bhi + (size_t)bn*ldb + k0; lds[1] = ldb;
        bases[2] = Blo + (size_t)bn*ldb + k0; lds[2] = ldb;
        #pragma unroll
        for (int t = 0; t < 3; t++){
            #pragma unroll
            for (int it = 0; it < 2; it++){
                int idx = it*256 + tid;
                int r = idx >> 2, c = idx & 3;
                cp_async16(sb + t*TILEB + (r*SPAD + c*8)*2,
                           bases[t] + (size_t)r*lds[t] + c*8);
            }
        }
        asm volatile("cp.async.commit_group;" ::: "memory");
    };

    load_stage(0, 0);
    if (KT > 1) load_stage(1, 1);

    const uint32_t sbase = (uint32_t)__cvta_generic_to_shared(smem);

    for (int kt = 0; kt < KT; kt++){
        const int buf = kt % NSTAGE;
        if (kt + 1 < KT) asm volatile("cp.async.wait_group 1;" ::: "memory");
        else             asm volatile("cp.async.wait_group 0;" ::: "memory");
        __syncthreads();
        if (kt + 2 < KT) load_stage((kt + 2) % NSTAGE, kt + 2);

        const uint32_t sA    = sbase + buf*STAGEB;
        const uint32_t sB_hi = sA + TILEB;
        const uint32_t sB_lo = sA + 2*TILEB;

        #pragma unroll
        for (int ks = 0; ks < 2; ks++){
            uint32_t aF[4][4], bH[2][4], bL[2][4];
            #pragma unroll
            for (int half = 0; half < 2; half++){
                int nrow = wn + half*16 + (lane & 7) + ((lane >> 4) << 3);
                int ncol = ks*16 + ((lane >> 3) & 1)*8;
                uint32_t off = (uint32_t)(nrow*SPAD + ncol)*2;
                ldsm4(bH[half], sB_hi + off);
                ldsm4(bL[half], sB_lo + off);
            }
            #pragma unroll
            for (int mf = 0; mf < 4; mf++){
                int arow = wm + mf*16 + (lane & 15);
                int acol = ks*16 + (lane >> 4)*8;
                ldsm4(aF[mf], sA + (uint32_t)(arow*SPAD + acol)*2);
            }
            #pragma unroll
            for (int mf = 0; mf < 4; mf++)
                #pragma unroll
                for (int nf = 0; nf < 4; nf++){
                    mma16816(acc[mf][nf], aF[mf], &bH[nf>>1][(nf&1)*2]);
                    mma16816(acc[mf][nf], aF[mf], &bL[nf>>1][(nf&1)*2]);
                }
        }
    }

    #pragma unroll
    for (int mf = 0; mf < 4; mf++){
        #pragma unroll
        for (int nf = 0; nf < 4; nf++){
            int row0 = bm + wm + mf*16 + (lane >> 2);
            int col0 = bn + wn + nf*8  + (lane & 3)*2;
            float b0 = 0.f, b1 = 0.f;
            if (bias){ b0 = bias[col0]; b1 = bias[col0+1]; }
            float2 v0 = make_float2(acc[mf][nf][0] + b0, acc[mf][nf][1] + b1);
            float2 v1 = make_float2(acc[mf][nf][2] + b0, acc[mf][nf][3] + b1);
            *(float2*)(Cc + (size_t)row0*ldc + col0)       = v0;
            *(float2*)(Cc + (size_t)(row0+8)*ldc + col0)   = v1;
        }
    }
}

// ---------------- prep: gates, decay, kk norm, pack scan inputs ----------------
__global__ void __launch_bounds__(512) prep_kernel(
        const float* __restrict__ vfirst,
        const float* __restrict__ w0, const float* __restrict__ a0, const float* __restrict__ v0,
        const float* __restrict__ k_k, const float* __restrict__ k_a, const float* __restrict__ r_k)
{
    int m = blockIdx.x;
    int b = m / TT, t = m % TT;
    int tid = threadIdx.x;
    int j0 = tid * 4;
    int h  = j0 >> 6;
    int kvidx = (h >> 2)*64 + (j0 & 63);

    const float* prow = g_proj + (size_t)m*N1;
    float4 rv = *(const float4*)(prow + j0);
    float4 kp = *(const float4*)(prow + 2048 + kvidx);
    float4 vp = *(const float4*)(prow + 2560 + kvidx);
    float4 wt = *(const float4*)(g_wterm + (size_t)m*CC + j0);
    float4 at = *(const float4*)(g_aterm + (size_t)m*CC + j0);
    float4 vt = *(const float4*)(g_vterm + (size_t)m*CC + j0);
    float4 vf = *(const float4*)(vfirst + (size_t)m*CC + j0);
    float4 kkw = *(const float4*)(k_k + j0);
    float4 kaw = *(const float4*)(k_a + j0);
    float4 rkw = *(const float4*)(r_k + j0);
    float4 w0v = *(const float4*)(w0 + j0);
    float4 a0v = *(const float4*)(a0 + j0);
    float4 v0v = *(const float4*)(v0 + j0);

    float rr[4]  = {rv.x, rv.y, rv.z, rv.w};
    float kpv[4] = {kp.x, kp.y, kp.z, kp.w};
    float vpv[4] = {vp.x, vp.y, vp.z, vp.w};
    float wtv[4] = {wt.x, wt.y, wt.z, wt.w};
    float atv[4] = {at.x, at.y, at.z, at.w};
    float vtv[4] = {vt.x, vt.y, vt.z, vt.w};
    float vfv[4] = {vf.x, vf.y, vf.z, vf.w};
    float kkwv[4]= {kkw.x,kkw.y,kkw.z,kkw.w};
    float kawv[4]= {kaw.x,kaw.y,kaw.z,kaw.w};
    float rkv[4] = {rkw.x,rkw.y,rkw.z,rkw.w};
    float w0a[4] = {w0v.x,w0v.y,w0v.z,w0v.w};
    float a0a[4] = {a0v.x,a0v.y,a0v.z,a0v.w};
    float v0a[4] = {v0v.x,v0v.y,v0v.z,v0v.w};

    float aga[4], dec[4], kkpre[4], kmod[4], vb[4];
    float nrm = 0.f;
    #pragma unroll
    for (int c=0;c<4;c++){
        float u = w0a[c] + wtv[c];
        float z = -u;
        float sp = (z > 20.f) ? z : log1pf(expf(z));
        float wraw = -sp - 0.6f;
        dec[c] = expf(-expf(wraw));
        float a = sigmoidf_(a0a[c] + atv[c]);
        aga[c] = a;
        kkpre[c] = kpv[c] * kkwv[c];
        nrm += kkpre[c]*kkpre[c];
        kmod[c] = kpv[c] * (1.f + (a - 1.f) * kawv[c]);
        float vsel = sigmoidf_(v0a[c] + vtv[c]);
        vb[c] = vpv[c] + (vfv[c] - vpv[c]) * vsel;
    }
    float tot = nrm;
    tot += __shfl_xor_sync(0xffffffffu, tot, 1);
    tot += __shfl_xor_sync(0xffffffffu, tot, 2);
    tot += __shfl_xor_sync(0xffffffffu, tot, 4);
    tot += __shfl_xor_sync(0xffffffffu, tot, 8);
    float inv = 1.f / fmaxf(sqrtf(tot), 1e-12f);

    float aav[4], bbv[4];
    float dsum = 0.f;
    #pragma unroll
    for (int c=0;c<4;c++){
        float kkn = kkpre[c]*inv;
        aav[c] = -kkn;
        bbv[c] = kkn*aga[c];
        dsum += rr[c]*kmod[c]*rkv[c];
    }
    float dtot = dsum;
    dtot += __shfl_xor_sync(0xffffffffu, dtot, 1);
    dtot += __shfl_xor_sync(0xffffffffu, dtot, 2);
    dtot += __shfl_xor_sync(0xffffffffu, dtot, 4);
    dtot += __shfl_xor_sync(0xffffffffu, dtot, 8);
    if ((tid & 15) == 0) g_bcoef[(size_t)m*HH + h] = dtot;

    size_t base = ((size_t)(b*HH + h)*TT + t)*384 + (j0 & 63);
    *(float4*)(g_packed + base +   0) = rv;
    *(float4*)(g_packed + base +  64) = make_float4(dec[0],dec[1],dec[2],dec[3]);
    *(float4*)(g_packed + base + 128) = make_float4(kmod[0],kmod[1],kmod[2],kmod[3]);
    *(float4*)(g_packed + base + 192) = make_float4(vb[0],vb[1],vb[2],vb[3]);
    *(float4*)(g_packed + base + 256) = make_float4(aav[0],aav[1],aav[2],aav[3]);
    *(float4*)(g_packed + base + 320) = make_float4(bbv[0],bbv[1],bbv[2],bbv[3]);
}

// ---------------- recurrent scan: one block (256 thr) per (b,h) ----------------
// 8-slot ring, ONE barrier per step; y stored contiguously as (b,h,t,i).
__global__ void __launch_bounds__(256,1) scan_kernel(const float* __restrict__ state0)
{
    __shared__ float buf[8][384];
    __shared__ float redA[64], redB[64];
    const int bh = blockIdx.x;
    const int tid = threadIdx.x;
    const int i = tid >> 2;
    const int q = tid & 3;
    const int kb = q * 16;

    float S[16];
    #pragma unroll
    for (int c=0;c<16;c++)
        S[c] = state0[((size_t)bh*64 + i)*64 + kb + c];

    const float* src = g_packed + (size_t)bh*TT*384;

    if (tid < 96) {
        #pragma unroll
        for (int s=0;s<4;s++){
            cp_async16(&buf[s][tid*4], src + (size_t)s*384 + tid*4);
            asm volatile("cp.async.commit_group;\n");
        }
    }

    float* yout = g_y + (size_t)bh*TT*64 + i;   // (b,h,t,i) layout
    float gsum = 0.f, gsq = 0.f;

    for (int t = 0; t < TT; t++) {
        if (tid < 96) asm volatile("cp.async.wait_group 3;\n");
        __syncthreads();
        const float* vbuf = buf[t & 7];

        float rr[16], dd[16], km[16], av[16], bv[16];
        #pragma unroll
        for (int m4=0;m4<4;m4++){
            float4 x0 = *(const float4*)&vbuf[  0 + kb + m4*4];
            float4 x1 = *(const float4*)&vbuf[ 64 + kb + m4*4];
            float4 x2 = *(const float4*)&vbuf[128 + kb + m4*4];
            float4 x4 = *(const float4*)&vbuf[256 + kb + m4*4];
            float4 x5 = *(const float4*)&vbuf[320 + kb + m4*4];
            rr[m4*4+0]=x0.x; rr[m4*4+1]=x0.y; rr[m4*4+2]=x0.z; rr[m4*4+3]=x0.w;
            dd[m4*4+0]=x1.x; dd[m4*4+1]=x1.y; dd[m4*4+2]=x1.z; dd[m4*4+3]=x1.w;
            km[m4*4+0]=x2.x; km[m4*4+1]=x2.y; km[m4*4+2]=x2.z; km[m4*4+3]=x2.w;
            av[m4*4+0]=x4.x; av[m4*4+1]=x4.y; av[m4*4+2]=x4.z; av[m4*4+3]=x4.w;
            bv[m4*4+0]=x5.x; bv[m4*4+1]=x5.y; bv[m4*4+2]=x5.z; bv[m4*4+3]=x5.w;
        }
        float vi = vbuf[192 + i];

        // 4-partial accumulation breaks the serial FMA dependency chain
        float sa0=0.f, sa1=0.f, sa2=0.f, sa3=0.f;
        #pragma unroll
        for (int c=0;c<16;c+=4){
            sa0 += S[c+0]*av[c+0];
            sa1 += S[c+1]*av[c+1];
            sa2 += S[c+2]*av[c+2];
            sa3 += S[c+3]*av[c+3];
        }
        float sa = (sa0+sa1) + (sa2+sa3);
        sa += __shfl_xor_sync(0xffffffffu, sa, 1);
        sa += __shfl_xor_sync(0xffffffffu, sa, 2);

        float yp0=0.f, yp1=0.f, yp2=0.f, yp3=0.f;
        #pragma unroll
        for (int c=0;c<16;c+=4){
            S[c+0] = S[c+0]*dd[c+0] + sa*bv[c+0] + vi*km[c+0];
            S[c+1] = S[c+1]*dd[c+1] + sa*bv[c+1] + vi*km[c+1];
            S[c+2] = S[c+2]*dd[c+2] + sa*bv[c+2] + vi*km[c+2];
            S[c+3] = S[c+3]*dd[c+3] + sa*bv[c+3] + vi*km[c+3];
            yp0 += S[c+0]*rr[c+0];
            yp1 += S[c+1]*rr[c+1];
            yp2 += S[c+2]*rr[c+2];
            yp3 += S[c+3]*rr[c+3];
        }
        float yp = (yp0+yp1) + (yp2+yp3);
        yp += __shfl_xor_sync(0xffffffffu, yp, 1);
        yp += __shfl_xor_sync(0xffffffffu, yp, 2);

        if (q == 0) {
            yout[(size_t)t*64] = yp;     // contiguous 256B line per (block, step)
            gsum += yp; gsq += yp*yp;
        }
        // prefetch t+4 into slot (t+4)&7: last read at step t-4, provably done
        if (tid < 96) {
            int tt = (t+4 < TT) ? (t+4) : (TT-1);
            cp_async16(&buf[(t+4)&7][tid*4], src + (size_t)tt*384 + tid*4);
            asm volatile("cp.async.commit_group;\n");
        }
    }

    if (q == 0) { redA[i] = gsum; redB[i] = gsq; }
    __syncthreads();
    if (tid < 32) {
        float s1 = redA[tid] + redA[tid+32];
        float s2 = redB[tid] + redB[tid+32];
        #pragma unroll
        for (int off=16; off>=1; off>>=1){
            s1 += __shfl_xor_sync(0xffffffffu, s1, off);
            s2 += __shfl_xor_sync(0xffffffffu, s2, off);
        }
        if (tid == 0) {
            float cnt = (float)(TT*NNd);
            float mean = s1 / cnt;
            float var  = s2 / cnt - mean*mean;
            g_gn[bh*2]   = mean;
            g_gn[bh*2+1] = rsqrtf(var + 0.00064f);
        }
    }
}

// ---------------- groupnorm apply + bonus, fused fp16 convert ----------------
__global__ void __launch_bounds__(512) apply_kernel(
        const float* __restrict__ ln_w, const float* __restrict__ ln_b)
{
    int m = blockIdx.x;
    int b = m / TT, t = m % TT;
    int tid = threadIdx.x;
    int j0 = tid * 4;
    int h = j0 >> 6;

    float mean = g_gn[(b*HH + h)*2];
    float rstd = g_gn[(b*HH + h)*2 + 1];
    float bc   = g_bcoef[(size_t)m*HH + h];

    // y is (b,h,t,i)
    float4 yv = *(const float4*)(g_y + ((size_t)(b*HH + h)*TT + t)*64 + (j0 & 63));
    float4 lw = *(const float4*)(ln_w + j0);
    float4 lb = *(const float4*)(ln_b + j0);
    size_t pbase = ((size_t)(b*HH + h)*TT + t)*384 + (j0 & 63);
    float4 vb = *(const float4*)(g_packed + pbase + 192);

    float o[4];
    o[0] = (yv.x - mean)*rstd*lw.x + lb.x + bc*vb.x;
    o[1] = (yv.y - mean)*rstd*lw.y + lb.y + bc*vb.y;
    o[2] = (yv.z - mean)*rstd*lw.z + lb.z + bc*vb.z;
    o[3] = (yv.w - mean)*rstd*lw.w + lb.w + bc*vb.w;

    __half hv[4];
    #pragma unroll
    for (int c=0;c<4;c++) hv[c] = __float2half_rn(o[c]);
    *(uint2*)(g_xxh + (size_t)m*CC + j0) = *(uint2*)hv;
}

// ---------------- launch ----------------
extern "C" void kernel_launch(void* const* d_in, const int* in_sizes, int n_in,
                              void* d_out, int out_size)
{
    const float* x      = (const float*)d_in[0];
    const float* vfirst = (const float*)d_in[1];
    const float* state  = (const float*)d_in[2];
    const float* Rw     = (const float*)d_in[3];
    const float* Rb     = (const float*)d_in[4];
    const float* Kw     = (const float*)d_in[5];
    const float* Kb     = (const float*)d_in[6];
    const float* Vw     = (const float*)d_in[7];
    const float* Vb     = (const float*)d_in[8];
    const float* Ow     = (const float*)d_in[9];
    const float* Ob     = (const float*)d_in[10];
    const float* w0     = (const float*)d_in[11];
    const float* w1     = (const float*)d_in[12];
    const float* w2     = (const float*)d_in[13];
    const float* a0     = (const float*)d_in[14];
    const float* a1     = (const float*)d_in[15];
    const float* a2     = (const float*)d_in[16];
    const float* v0     = (const float*)d_in[17];
    const float* v1     = (const float*)d_in[18];
    const float* v2     = (const float*)d_in[19];
    const float* k_k    = (const float*)d_in[20];
    const float* k_a    = (const float*)d_in[21];
    const float* r_k    = (const float*)d_in[22];
    const float* ln_w   = (const float*)d_in[23];
    const float* ln_b   = (const float*)d_in[24];
    float* out = (float*)d_out;

    cudaFuncSetAttribute(hmma_nt, cudaFuncAttributeMaxDynamicSharedMemorySize, NSTAGE*STAGEB);

    float *proj, *wterm, *aterm, *vterm, *bias1;
    __half *xh, *b1hi, *b1lo, *hh;
    __half *w2hi, *w2lo, *a2hi, *a2lo, *v2hi, *v2lo;
    __half *xxh, *ohi, *olo;
    cudaGetSymbolAddress((void**)&proj,  g_proj);
    cudaGetSymbolAddress((void**)&wterm, g_wterm);
    cudaGetSymbolAddress((void**)&aterm, g_aterm);
    cudaGetSymbolAddress((void**)&vterm, g_vterm);
    cudaGetSymbolAddress((void**)&bias1, g_bias1);
    cudaGetSymbolAddress((void**)&xh,    g_xh);
    cudaGetSymbolAddress((void**)&b1hi,  g_b1hi);
    cudaGetSymbolAddress((void**)&b1lo,  g_b1lo);
    cudaGetSymbolAddress((void**)&hh,    g_hidh);
    cudaGetSymbolAddress((void**)&w2hi,  g_w2hi);
    cudaGetSymbolAddress((void**)&w2lo,  g_w2lo);
    cudaGetSymbolAddress((void**)&a2hi,  g_a2hi);
    cudaGetSymbolAddress((void**)&a2lo,  g_a2lo);
    cudaGetSymbolAddress((void**)&v2hi,  g_v2hi);
    cudaGetSymbolAddress((void**)&v2lo,  g_v2lo);
    cudaGetSymbolAddress((void**)&xxh,   g_xxh);
    cudaGetSymbolAddress((void**)&ohi,   g_ohi);
    cudaGetSymbolAddress((void**)&olo,   g_olo);

    // weight packing (hi+lo) + activation convert (hi only)
    pack_b1<<<(int)(((size_t)N1*CC + 255)/256), 256>>>(Rw, Rb, Kw, Kb, Vw, Vb, w1, a1, v1);
    pack_b2<<<(CC*64 + 255)/256, 256>>>(w2, a2, v2);
    split_ox<<<2048, 256>>>(Ow, x);

    // GEMM1: proj = x @ [R|K|V|w1|a1|v1]^T + bias1   (M=4096, N=3328, K=2048)
    {
        dim3 g(N1/128, MM/128);
        hmma_nt<<<g, 256, NSTAGE*STAGEB>>>(xh, CC, b1hi, b1lo, CC, bias1, proj, N1, CC/32);
    }
    hid_cvt<<<(int)(((size_t)MM*HIDP + 255)/256), 256>>>();

    // stage-2 small-K GEMMs (K=64 -> KT=2)
    {
        dim3 g(CC/128, MM/128);
        hmma_nt<<<g, 256, NSTAGE*STAGEB>>>(hh,       HIDP, w2hi, w2lo, 64, nullptr, wterm, CC, 2);
        hmma_nt<<<g, 256, NSTAGE*STAGEB>>>(hh + 64,  HIDP, a2hi, a2lo, 64, nullptr, aterm, CC, 2);
        hmma_nt<<<g, 256, NSTAGE*STAGEB>>>(hh + 128, HIDP, v2hi, v2lo, 64, nullptr, vterm, CC, 2);
    }

    prep_kernel<<<MM, 512>>>(vfirst, w0, a0, v0, k_k, k_a, r_k);
    scan_kernel<<<BB*HH, 256>>>(state);
    apply_kernel<<<MM, 512>>>(ln_w, ln_b);

    // out = xx @ O^T + O_bias   (M=4096, N=2048, K=2048)
    {
        dim3 g(CC/128, MM/128);
        hmma_nt<<<g, 256, NSTAGE*STAGEB>>>(xxh, CC, ohi, olo, CC, Ob, out, CC, CC/32);
    }
}

// round 14
// speedup vs baseline: 1.5950x; 1.5950x over previous
#include <cuda_runtime.h>
#include <cuda_fp16.h>
#include <math.h>
#include <stdint.h>

#define BB 4
#define TT 1024
#define CC 2048
#define HH 32
#define NNd 64
#define KVD 512
#define MM (BB*TT)      // 4096 tokens
#define N1 3328         // combined GEMM1 N: 2048(R)+512(K)+512(V)+160(lora)+96 pad
#define HIDP 192        // hidden padded cols

// ---------------- scratch (static device arrays; no allocation) ----------------
__device__ __align__(128) __half g_xh[(size_t)MM*CC];
__device__ __align__(128) __half g_b1hi[(size_t)N1*CC];
__device__ __align__(128) __half g_b1lo[(size_t)N1*CC];
__device__ __align__(128) float g_bias1[N1];
__device__ __align__(128) float g_proj[(size_t)MM*N1];
__device__ __align__(128) __half g_hidh[(size_t)MM*HIDP];
__device__ __align__(128) __half g_w2hi[CC*64];
__device__ __align__(128) __half g_w2lo[CC*64];
__device__ __align__(128) __half g_a2hi[CC*64];
__device__ __align__(128) __half g_a2lo[CC*64];
__device__ __align__(128) __half g_v2hi[CC*64];
__device__ __align__(128) __half g_v2lo[CC*64];
__device__ __align__(128) float g_wterm[(size_t)MM*CC];
__device__ __align__(128) float g_aterm[(size_t)MM*CC];
__device__ __align__(128) float g_vterm[(size_t)MM*CC];
__device__ __align__(128) float g_packed[(size_t)BB*HH*TT*384];
__device__ __align__(128) float g_y[(size_t)MM*CC];      // layout (b,h,t,i)
__device__ __align__(128) __half g_xxh[(size_t)MM*CC];
__device__ __align__(128) __half g_ohi[(size_t)CC*CC];
__device__ __align__(128) __half g_olo[(size_t)CC*CC];
__device__ __align__(128) float g_bcoef[(size_t)MM*HH];
__device__ __align__(128) float g_gn[BB*HH*2];

// ---------------- helpers ----------------
__device__ __forceinline__ float sigmoidf_(float x){ return 1.0f/(1.0f + expf(-x)); }

__device__ __forceinline__ void cp_async16(void* smem, const void* gmem){
    unsigned s = (unsigned)__cvta_generic_to_shared(smem);
    asm volatile("cp.async.cg.shared.global [%0], [%1], 16;\n" :: "r"(s), "l"(gmem));
}

__device__ __forceinline__ void split2h(float v, __half* hi, __half* lo){
    __half h = __float2half_rn(v);
    *hi = h;
    *lo = __float2half_rn(v - __half2float(h));
}

// ---------------- mma.sync helpers (legacy tensor path; plain sm_103 target) ----
__device__ __forceinline__ void ldsm4(uint32_t* r, uint32_t addr){
    asm volatile("ldmatrix.sync.aligned.m8n8.x4.shared.b16 {%0,%1,%2,%3}, [%4];"
                 : "=r"(r[0]), "=r"(r[1]), "=r"(r[2]), "=r"(r[3]) : "r"(addr));
}

__device__ __forceinline__ void mma16816(float* c, const uint32_t* a, const uint32_t* b){
    asm volatile(
        "mma.sync.aligned.m16n8k16.row.col.f32.f16.f16.f32 "
        "{%0,%1,%2,%3}, {%4,%5,%6,%7}, {%8,%9}, {%0,%1,%2,%3};"
        : "+f"(c[0]), "+f"(c[1]), "+f"(c[2]), "+f"(c[3])
        : "r"(a[0]), "r"(a[1]), "r"(a[2]), "r"(a[3]), "r"(b[0]), "r"(b[1]));
}

// ---------------- packing / convert kernels ----------------
__global__ void pack_b1(const float* __restrict__ R,  const float* __restrict__ Rb,
                        const float* __restrict__ Kw, const float* __restrict__ Kb,
                        const float* __restrict__ Vw, const float* __restrict__ Vb,
                        const float* __restrict__ w1, const float* __restrict__ a1,
                        const float* __restrict__ v1)
{
    size_t idx = (size_t)blockIdx.x*blockDim.x + threadIdx.x;
    if (idx < N1) {
        float bv = 0.f;
        if (idx < 2048) bv = Rb[idx];
        else if (idx < 2560) bv = Kb[idx-2048];
        else if (idx < 3072) bv = Vb[idx-2560];
        g_bias1[idx] = bv;
    }
    if (idx >= (size_t)N1*CC) return;
    int n = (int)(idx / CC), k = (int)(idx % CC);
    float v = 0.f;
    if      (n < 2048) v = R [(size_t)n*CC + k];
    else if (n < 2560) v = Kw[(size_t)(n-2048)*CC + k];
    else if (n < 3072) v = Vw[(size_t)(n-2560)*CC + k];
    else if (n < 3136) v = w1[(size_t)k*64 + (n-3072)];
    else if (n < 3200) v = a1[(size_t)k*64 + (n-3136)];
    else if (n < 3232) v = v1[(size_t)k*32 + (n-3200)];
    split2h(v, &g_b1hi[idx], &g_b1lo[idx]);
}

__global__ void pack_b2(const float* __restrict__ w2, const float* __restrict__ a2,
                        const float* __restrict__ v2)
{
    int idx = blockIdx.x*blockDim.x + threadIdx.x;
    if (idx >= CC*64) return;
    int n = idx / 64, k = idx % 64;
    split2h(w2[(size_t)k*CC + n], &g_w2hi[idx], &g_w2lo[idx]);
    split2h(a2[(size_t)k*CC + n], &g_a2hi[idx], &g_a2lo[idx]);
    float vv = (k < 32) ? v2[(size_t)k*CC + n] : 0.f;
    split2h(vv, &g_v2hi[idx], &g_v2lo[idx]);
}

// merged: split Ow into hi/lo AND convert x to fp16
__global__ void split_ox(const float* __restrict__ Ow, const float* __restrict__ x)
{
    size_t stride = (size_t)gridDim.x * blockDim.x;
    size_t i0 = (size_t)blockIdx.x*blockDim.x + threadIdx.x;
    for (size_t i = i0; i < (size_t)CC*CC; i += stride)
        split2h(Ow[i], &g_ohi[i], &g_olo[i]);
    for (size_t i = i0; i < (size_t)MM*CC/4; i += stride){
        float4 v = *(const float4*)(x + i*4);
        __half h[4] = {__float2half_rn(v.x), __float2half_rn(v.y),
                       __float2half_rn(v.z), __float2half_rn(v.w)};
        *(uint2*)(g_xh + i*4) = *(uint2*)h;
    }
}

__global__ void hid_cvt()
{
    size_t idx = (size_t)blockIdx.x*blockDim.x + threadIdx.x;
    if (idx >= (size_t)MM*HIDP) return;
    int m = (int)(idx / HIDP), j = (int)(idx % HIDP);
    const float* row = g_proj + (size_t)m*N1 + 3072;
    float v = 0.f;
    if (j < 64)       v = tanhf(row[j]);
    else if (j < 160) v = row[j];
    g_hidh[idx] = __float2half_rn(v);
}

// ---------------- fp16 2-product HMMA NT GEMM: C = Ah*(Bhi+Blo)^T + bias --------
// BM=BN=128, BK=32, 256 threads (8 warps, warp tile 64x32).
// 3-stage cp.async ring, ONE __syncthreads per K-tile.
#define SPAD 40                     // smem row stride in fp16 elems (32 + 8 pad)
#define TILEB (128*SPAD*2)          // 10240 B per operand tile
#define STAGEB (3*TILEB)            // 30720 B per stage (A, Bhi, Blo)
#define NSTAGE 3

__global__ void __launch_bounds__(256,2) hmma_nt(
    const __half* __restrict__ Ah, int lda,
    const __half* __restrict__ Bhi, const __half* __restrict__ Blo, int ldb,
    const float* __restrict__ bias, float* __restrict__ Cc, int ldc, int KT)
{
    extern __shared__ __align__(128) char smem[];
    const int tid  = threadIdx.x;
    const int warp = tid >> 5;
    const int lane = tid & 31;
    const int bm   = blockIdx.y * 128;
    const int bn   = blockIdx.x * 128;
    const int wm   = (warp & 1) * 64;
    const int wn   = (warp >> 1) * 32;

    float acc[4][4][4];
    #pragma unroll
    for (int a=0;a<4;a++)
        #pragma unroll
        for (int b=0;b<4;b++)
            #pragma unroll
            for (int c=0;c<4;c++) acc[a][b][c]=0.f;

    auto load_stage = [&](int stage, int kt){
        const int k0 = kt * 32;
        char* sb = smem + stage * STAGEB;
        const __half* bases[3];
        int lds[3];
        bases[0] = Ah  + (size_t)bm*lda + k0; lds[0] = lda;
        bases[1] = Bhi + (size_t)bn*ldb + k0; lds[1] = ldb;
        bases[2] = Blo + (size_t)bn*ldb + k0; lds[2] = ldb;
        #pragma unroll
        for (int t = 0; t < 3; t++){
            #pragma unroll
            for (int it = 0; it < 2; it++){
                int idx = it*256 + tid;
                int r = idx >> 2, c = idx & 3;
                cp_async16(sb + t*TILEB + (r*SPAD + c*8)*2,
                           bases[t] + (size_t)r*lds[t] + c*8);
            }
        }
        asm volatile("cp.async.commit_group;" ::: "memory");
    };

    load_stage(0, 0);
    if (KT > 1) load_stage(1, 1);

    const uint32_t sbase = (uint32_t)__cvta_generic_to_shared(smem);

    for (int kt = 0; kt < KT; kt++){
        const int buf = kt % NSTAGE;
        if (kt + 1 < KT) asm volatile("cp.async.wait_group 1;" ::: "memory");
        else             asm volatile("cp.async.wait_group 0;" ::: "memory");
        __syncthreads();
        if (kt + 2 < KT) load_stage((kt + 2) % NSTAGE, kt + 2);

        const uint32_t sA    = sbase + buf*STAGEB;
        const uint32_t sB_hi = sA + TILEB;
        const uint32_t sB_lo = sA + 2*TILEB;

        #pragma unroll
        for (int ks = 0; ks < 2; ks++){
            uint32_t aF[4][4], bH[2][4], bL[2][4];
            #pragma unroll
            for (int half = 0; half < 2; half++){
                int nrow = wn + half*16 + (lane & 7) + ((lane >> 4) << 3);
                int ncol = ks*16 + ((lane >> 3) & 1)*8;
                uint32_t off = (uint32_t)(nrow*SPAD + ncol)*2;
                ldsm4(bH[half], sB_hi + off);
                ldsm4(bL[half], sB_lo + off);
            }
            #pragma unroll
            for (int mf = 0; mf < 4; mf++){
                int arow = wm + mf*16 + (lane & 15);
                int acol = ks*16 + (lane >> 4)*8;
                ldsm4(aF[mf], sA + (uint32_t)(arow*SPAD + acol)*2);
            }
            #pragma unroll
            for (int mf = 0; mf < 4; mf++)
                #pragma unroll
                for (int nf = 0; nf < 4; nf++){
                    mma16816(acc[mf][nf], aF[mf], &bH[nf>>1][(nf&1)*2]);
                    mma16816(acc[mf][nf], aF[mf], &bL[nf>>1][(nf&1)*2]);
                }
        }
    }

    #pragma unroll
    for (int mf = 0; mf < 4; mf++){
        #pragma unroll
        for (int nf = 0; nf < 4; nf++){
            int row0 = bm + wm + mf*16 + (lane >> 2);
            int col0 = bn + wn + nf*8  + (lane & 3)*2;
            float b0 = 0.f, b1 = 0.f;
            if (bias){ b0 = bias[col0]; b1 = bias[col0+1]; }
            float2 v0 = make_float2(acc[mf][nf][0] + b0, acc[mf][nf][1] + b1);
            float2 v1 = make_float2(acc[mf][nf][2] + b0, acc[mf][nf][3] + b1);
            *(float2*)(Cc + (size_t)row0*ldc + col0)       = v0;
            *(float2*)(Cc + (size_t)(row0+8)*ldc + col0)   = v1;
        }
    }
}

// ---------------- prep: gates, decay, kk norm, pack scan inputs ----------------
__global__ void __launch_bounds__(512) prep_kernel(
        const float* __restrict__ vfirst,
        const float* __restrict__ w0, const float* __restrict__ a0, const float* __restrict__ v0,
        const float* __restrict__ k_k, const float* __restrict__ k_a, const float* __restrict__ r_k)
{
    int m = blockIdx.x;
    int b = m / TT, t = m % TT;
    int tid = threadIdx.x;
    int j0 = tid * 4;
    int h  = j0 >> 6;
    int kvidx = (h >> 2)*64 + (j0 & 63);

    const float* prow = g_proj + (size_t)m*N1;
    float4 rv = *(const float4*)(prow + j0);
    float4 kp = *(const float4*)(prow + 2048 + kvidx);
    float4 vp = *(const float4*)(prow + 2560 + kvidx);
    float4 wt = *(const float4*)(g_wterm + (size_t)m*CC + j0);
    float4 at = *(const float4*)(g_aterm + (size_t)m*CC + j0);
    float4 vt = *(const float4*)(g_vterm + (size_t)m*CC + j0);
    float4 vf = *(const float4*)(vfirst + (size_t)m*CC + j0);
    float4 kkw = *(const float4*)(k_k + j0);
    float4 kaw = *(const float4*)(k_a + j0);
    float4 rkw = *(const float4*)(r_k + j0);
    float4 w0v = *(const float4*)(w0 + j0);
    float4 a0v = *(const float4*)(a0 + j0);
    float4 v0v = *(const float4*)(v0 + j0);

    float rr[4]  = {rv.x, rv.y, rv.z, rv.w};
    float kpv[4] = {kp.x, kp.y, kp.z, kp.w};
    float vpv[4] = {vp.x, vp.y, vp.z, vp.w};
    float wtv[4] = {wt.x, wt.y, wt.z, wt.w};
    float atv[4] = {at.x, at.y, at.z, at.w};
    float vtv[4] = {vt.x, vt.y, vt.z, vt.w};
    float vfv[4] = {vf.x, vf.y, vf.z, vf.w};
    float kkwv[4]= {kkw.x,kkw.y,kkw.z,kkw.w};
    float kawv[4]= {kaw.x,kaw.y,kaw.z,kaw.w};
    float rkv[4] = {rkw.x,rkw.y,rkw.z,rkw.w};
    float w0a[4] = {w0v.x,w0v.y,w0v.z,w0v.w};
    float a0a[4] = {a0v.x,a0v.y,a0v.z,a0v.w};
    float v0a[4] = {v0v.x,v0v.y,v0v.z,v0v.w};

    float aga[4], dec[4], kkpre[4], kmod[4], vb[4];
    float nrm = 0.f;
    #pragma unroll
    for (int c=0;c<4;c++){
        float u = w0a[c] + wtv[c];
        float z = -u;
        float sp = (z > 20.f) ? z : log1pf(expf(z));
        float wraw = -sp - 0.6f;
        dec[c] = expf(-expf(wraw));
        float a = sigmoidf_(a0a[c] + atv[c]);
        aga[c] = a;
        kkpre[c] = kpv[c] * kkwv[c];
        nrm += kkpre[c]*kkpre[c];
        kmod[c] = kpv[c] * (1.f + (a - 1.f) * kawv[c]);
        float vsel = sigmoidf_(v0a[c] + vtv[c]);
        vb[c] = vpv[c] + (vfv[c] - vpv[c]) * vsel;
    }
    float tot = nrm;
    tot += __shfl_xor_sync(0xffffffffu, tot, 1);
    tot += __shfl_xor_sync(0xffffffffu, tot, 2);
    tot += __shfl_xor_sync(0xffffffffu, tot, 4);
    tot += __shfl_xor_sync(0xffffffffu, tot, 8);
    float inv = 1.f / fmaxf(sqrtf(tot), 1e-12f);

    float aav[4], bbv[4];
    float dsum = 0.f;
    #pragma unroll
    for (int c=0;c<4;c++){
        float kkn = kkpre[c]*inv;
        aav[c] = -kkn;
        bbv[c] = kkn*aga[c];
        dsum += rr[c]*kmod[c]*rkv[c];
    }
    float dtot = dsum;
    dtot += __shfl_xor_sync(0xffffffffu, dtot, 1);
    dtot += __shfl_xor_sync(0xffffffffu, dtot, 2);
    dtot += __shfl_xor_sync(0xffffffffu, dtot, 4);
    dtot += __shfl_xor_sync(0xffffffffu, dtot, 8);
    if ((tid & 15) == 0) g_bcoef[(size_t)m*HH + h] = dtot;

    size_t base = ((size_t)(b*HH + h)*TT + t)*384 + (j0 & 63);
    *(float4*)(g_packed + base +   0) = rv;
    *(float4*)(g_packed + base +  64) = make_float4(dec[0],dec[1],dec[2],dec[3]);
    *(float4*)(g_packed + base + 128) = make_float4(kmod[0],kmod[1],kmod[2],kmod[3]);
    *(float4*)(g_packed + base + 192) = make_float4(vb[0],vb[1],vb[2],vb[3]);
    *(float4*)(g_packed + base + 256) = make_float4(aav[0],aav[1],aav[2],aav[3]);
    *(float4*)(g_packed + base + 320) = make_float4(bbv[0],bbv[1],bbv[2],bbv[3]);
}

// ---------------- recurrent scan: one block (256 thr) per (b,h) ----------------
// 8-slot ring, ONE barrier per step; y stored contiguously as (b,h,t,i).
__global__ void __launch_bounds__(256,1) scan_kernel(const float* __restrict__ state0)
{
    __shared__ float buf[8][384];
    __shared__ float redA[64], redB[64];
    const int bh = blockIdx.x;
    const int tid = threadIdx.x;
    const int i = tid >> 2;
    const int q = tid & 3;
    const int kb = q * 16;

    float S[16];
    #pragma unroll
    for (int c=0;c<16;c++)
        S[c] = state0[((size_t)bh*64 + i)*64 + kb + c];

    const float* src = g_packed + (size_t)bh*TT*384;

    if (tid < 96) {
        #pragma unroll
        for (int s=0;s<4;s++){
            cp_async16(&buf[s][tid*4], src + (size_t)s*384 + tid*4);
            asm volatile("cp.async.commit_group;\n");
        }
    }

    float* yout = g_y + (size_t)bh*TT*64 + i;   // (b,h,t,i) layout
    float gsum = 0.f, gsq = 0.f;

    for (int t = 0; t < TT; t++) {
        if (tid < 96) asm volatile("cp.async.wait_group 3;\n");
        __syncthreads();
        const float* vbuf = buf[t & 7];

        float rr[16], dd[16], km[16], av[16], bv[16];
        #pragma unroll
        for (int m4=0;m4<4;m4++){
            float4 x0 = *(const float4*)&vbuf[  0 + kb + m4*4];
            float4 x1 = *(const float4*)&vbuf[ 64 + kb + m4*4];
            float4 x2 = *(const float4*)&vbuf[128 + kb + m4*4];
            float4 x4 = *(const float4*)&vbuf[256 + kb + m4*4];
            float4 x5 = *(const float4*)&vbuf[320 + kb + m4*4];
            rr[m4*4+0]=x0.x; rr[m4*4+1]=x0.y; rr[m4*4+2]=x0.z; rr[m4*4+3]=x0.w;
            dd[m4*4+0]=x1.x; dd[m4*4+1]=x1.y; dd[m4*4+2]=x1.z; dd[m4*4+3]=x1.w;
            km[m4*4+0]=x2.x; km[m4*4+1]=x2.y; km[m4*4+2]=x2.z; km[m4*4+3]=x2.w;
            av[m4*4+0]=x4.x; av[m4*4+1]=x4.y; av[m4*4+2]=x4.z; av[m4*4+3]=x4.w;
            bv[m4*4+0]=x5.x; bv[m4*4+1]=x5.y; bv[m4*4+2]=x5.z; bv[m4*4+3]=x5.w;
        }
        float vi = vbuf[192 + i];

        // 4-partial accumulation breaks the serial FMA dependency chain
        float sa0=0.f, sa1=0.f, sa2=0.f, sa3=0.f;
        #pragma unroll
        for (int c=0;c<16;c+=4){
            sa0 += S[c+0]*av[c+0];
            sa1 += S[c+1]*av[c+1];
            sa2 += S[c+2]*av[c+2];
            sa3 += S[c+3]*av[c+3];
        }
        float sa = (sa0+sa1) + (sa2+sa3);
        sa += __shfl_xor_sync(0xffffffffu, sa, 1);
        sa += __shfl_xor_sync(0xffffffffu, sa, 2);

        float yp0=0.f, yp1=0.f, yp2=0.f, yp3=0.f;
        #pragma unroll
        for (int c=0;c<16;c+=4){
            S[c+0] = S[c+0]*dd[c+0] + sa*bv[c+0] + vi*km[c+0];
            S[c+1] = S[c+1]*dd[c+1] + sa*bv[c+1] + vi*km[c+1];
            S[c+2] = S[c+2]*dd[c+2] + sa*bv[c+2] + vi*km[c+2];
            S[c+3] = S[c+3]*dd[c+3] + sa*bv[c+3] + vi*km[c+3];
            yp0 += S[c+0]*rr[c+0];
            yp1 += S[c+1]*rr[c+1];
            yp2 += S[c+2]*rr[c+2];
            yp3 += S[c+3]*rr[c+3];
        }
        float yp = (yp0+yp1) + (yp2+yp3);
        yp += __shfl_xor_sync(0xffffffffu, yp, 1);
        yp += __shfl_xor_sync(0xffffffffu, yp, 2);

        if (q == 0) {
            yout[(size_t)t*64] = yp;     // contiguous 256B line per (block, step)
            gsum += yp; gsq += yp*yp;
        }
        // prefetch t+4 into slot (t+4)&7: last read at step t-4, provably done
        if (tid < 96) {
            int tt = (t+4 < TT) ? (t+4) : (TT-1);
            cp_async16(&buf[(t+4)&7][tid*4], src + (size_t)tt*384 + tid*4);
            asm volatile("cp.async.commit_group;\n");
        }
    }

    if (q == 0) { redA[i] = gsum; redB[i] = gsq; }
    __syncthreads();
    if (tid < 32) {
        float s1 = redA[tid] + redA[tid+32];
        float s2 = redB[tid] + redB[tid+32];
        #pragma unroll
        for (int off=16; off>=1; off>>=1){
            s1 += __shfl_xor_sync(0xffffffffu, s1, off);
            s2 += __shfl_xor_sync(0xffffffffu, s2, off);
        }
        if (tid == 0) {
            float cnt = (float)(TT*NNd);
            float mean = s1 / cnt;
            float var  = s2 / cnt - mean*mean;
            g_gn[bh*2]   = mean;
            g_gn[bh*2+1] = rsqrtf(var + 0.00064f);
        }
    }
}

// ---------------- groupnorm apply + bonus, fused fp16 convert ----------------
__global__ void __launch_bounds__(512) apply_kernel(
        const float* __restrict__ ln_w, const float* __restrict__ ln_b)
{
    int m = blockIdx.x;
    int b = m / TT, t = m % TT;
    int tid = threadIdx.x;
    int j0 = tid * 4;
    int h = j0 >> 6;

    float mean = g_gn[(b*HH + h)*2];
    float rstd = g_gn[(b*HH + h)*2 + 1];
    float bc   = g_bcoef[(size_t)m*HH + h];

    // y is (b,h,t,i)
    float4 yv = *(const float4*)(g_y + ((size_t)(b*HH + h)*TT + t)*64 + (j0 & 63));
    float4 lw = *(const float4*)(ln_w + j0);
    float4 lb = *(const float4*)(ln_b + j0);
    size_t pbase = ((size_t)(b*HH + h)*TT + t)*384 + (j0 & 63);
    float4 vb = *(const float4*)(g_packed + pbase + 192);

    float o[4];
    o[0] = (yv.x - mean)*rstd*lw.x + lb.x + bc*vb.x;
    o[1] = (yv.y - mean)*rstd*lw.y + lb.y + bc*vb.y;
    o[2] = (yv.z - mean)*rstd*lw.z + lb.z + bc*vb.z;
    o[3] = (yv.w - mean)*rstd*lw.w + lb.w + bc*vb.w;

    __half hv[4];
    #pragma unroll
    for (int c=0;c<4;c++) hv[c] = __float2half_rn(o[c]);
    *(uint2*)(g_xxh + (size_t)m*CC + j0) = *(uint2*)hv;
}

// ---------------- launch ----------------
extern "C" void kernel_launch(void* const* d_in, const int* in_sizes, int n_in,
                              void* d_out, int out_size)
{
    const float* x      = (const float*)d_in[0];
    const float* vfirst = (const float*)d_in[1];
    const float* state  = (const float*)d_in[2];
    const float* Rw     = (const float*)d_in[3];
    const float* Rb     = (const float*)d_in[4];
    const float* Kw     = (const float*)d_in[5];
    const float* Kb     = (const float*)d_in[6];
    const float* Vw     = (const float*)d_in[7];
    const float* Vb     = (const float*)d_in[8];
    const float* Ow     = (const float*)d_in[9];
    const float* Ob     = (const float*)d_in[10];
    const float* w0     = (const float*)d_in[11];
    const float* w1     = (const float*)d_in[12];
    const float* w2     = (const float*)d_in[13];
    const float* a0     = (const float*)d_in[14];
    const float* a1     = (const float*)d_in[15];
    const float* a2     = (const float*)d_in[16];
    const float* v0     = (const float*)d_in[17];
    const float* v1     = (const float*)d_in[18];
    const float* v2     = (const float*)d_in[19];
    const float* k_k    = (const float*)d_in[20];
    const float* k_a    = (const float*)d_in[21];
    const float* r_k    = (const float*)d_in[22];
    const float* ln_w   = (const float*)d_in[23];
    const float* ln_b   = (const float*)d_in[24];
    float* out = (float*)d_out;

    cudaFuncSetAttribute(hmma_nt, cudaFuncAttributeMaxDynamicSharedMemorySize, NSTAGE*STAGEB);

    float *proj, *wterm, *aterm, *vterm, *bias1;
    __half *xh, *b1hi, *b1lo, *hh;
    __half *w2hi, *w2lo, *a2hi, *a2lo, *v2hi, *v2lo;
    __half *xxh, *ohi, *olo;
    cudaGetSymbolAddress((void**)&proj,  g_proj);
    cudaGetSymbolAddress((void**)&wterm, g_wterm);
    cudaGetSymbolAddress((void**)&aterm, g_aterm);
    cudaGetSymbolAddress((void**)&vterm, g_vterm);
    cudaGetSymbolAddress((void**)&bias1, g_bias1);
    cudaGetSymbolAddress((void**)&xh,    g_xh);
    cudaGetSymbolAddress((void**)&b1hi,  g_b1hi);
    cudaGetSymbolAddress((void**)&b1lo,  g_b1lo);
    cudaGetSymbolAddress((void**)&hh,    g_hidh);
    cudaGetSymbolAddress((void**)&w2hi,  g_w2hi);
    cudaGetSymbolAddress((void**)&w2lo,  g_w2lo);
    cudaGetSymbolAddress((void**)&a2hi,  g_a2hi);
    cudaGetSymbolAddress((void**)&a2lo,  g_a2lo);
    cudaGetSymbolAddress((void**)&v2hi,  g_v2hi);
    cudaGetSymbolAddress((void**)&v2lo,  g_v2lo);
    cudaGetSymbolAddress((void**)&xxh,   g_xxh);
    cudaGetSymbolAddress((void**)&ohi,   g_ohi);
    cudaGetSymbolAddress((void**)&olo,   g_olo);

    // weight packing (hi+lo) + activation convert (hi only)
    pack_b1<<<(int)(((size_t)N1*CC + 255)/256), 256>>>(Rw, Rb, Kw, Kb, Vw, Vb, w1, a1, v1);
    pack_b2<<<(CC*64 + 255)/256, 256>>>(w2, a2, v2);
    split_ox<<<2048, 256>>>(Ow, x);

    // GEMM1: proj = x @ [R|K|V|w1|a1|v1]^T + bias1   (M=4096, N=3328, K=2048)
    {
        dim3 g(N1/128, MM/128);
        hmma_nt<<<g, 256, NSTAGE*STAGEB>>>(xh, CC, b1hi, b1lo, CC, bias1, proj, N1, CC/32);
    }
    hid_cvt<<<(int)(((size_t)MM*HIDP + 255)/256), 256>>>();

    // stage-2 small-K GEMMs (K=64 -> KT=2)
    {
        dim3 g(CC/128, MM/128);
        hmma_nt<<<g, 256, NSTAGE*STAGEB>>>(hh,       HIDP, w2hi, w2lo, 64, nullptr, wterm, CC, 2);
        hmma_nt<<<g, 256, NSTAGE*STAGEB>>>(hh + 64,  HIDP, a2hi, a2lo, 64, nullptr, aterm, CC, 2);
        hmma_nt<<<g, 256, NSTAGE*STAGEB>>>(hh + 128, HIDP, v2hi, v2lo, 64, nullptr, vterm, CC, 2);
    }

    prep_kernel<<<MM, 512>>>(vfirst, w0, a0, v0, k_k, k_a, r_k);
    scan_kernel<<<BB*HH, 256>>>(state);
    apply_kernel<<<MM, 512>>>(ln_w, ln_b);

    // out = xx @ O^T + O_bias   (M=4096, N=2048, K=2048)
    {
        dim3 g(CC/128, MM/128);
        hmma_nt<<<g, 256, NSTAGE*STAGEB>>>(xxh, CC, ohi, olo, CC, Ob, out, CC, CC/32);
    }
}